// round 12
// baseline (speedup 1.0000x reference)
#include <cuda_runtime.h>
#include <math.h>

// Problem constants (from reference)
#define BATCH       64
#define NUM_HEADS   32
#define HEAD_DIM    128
#define KVH         8
#define G           4       // query heads per kv head
#define BS          16      // tokens per KV block
#define MAXB        128     // max blocks per sequence
#define LMAX        2048    // MAXB * BS
#define QK_SCALE    0.08838834764831845f

// Split-K (flash-decode) parameters
#define CHUNK       256                 // tokens per partition (one wave of CTAs)
#define NPART       (LMAX / CHUNK)      // 8
#define CBLKS       (CHUNK / BS)        // 16 KV blocks per partition

#define NTHREADS    128
#define NWARPS      (NTHREADS / 32)     // 4

// Scratch for partial results (no allocation allowed -> __device__ globals)
// layout: [B*KVH][NPART][G][HEAD_DIM]
__device__ float g_pout[BATCH * KVH * NPART * G * HEAD_DIM];   // 8.4 MB
__device__ float g_pm[BATCH * KVH * NPART * G];                // chunk max
__device__ float g_pl[BATCH * KVH * NPART * G];                // chunk expsum

// ---------------------------------------------------------------------------
// Kernel 1: per-(b, kvh, partition) local attention over <=256 tokens.
// Both phases warp-per-token / lane-owns-d4 (coalesced 512B row reads).
// Phase 1 is 2-way token-unrolled for MLP=2 per warp.
// ---------------------------------------------------------------------------
__global__ __launch_bounds__(NTHREADS) void pa_partial_kernel(
    const float* __restrict__ q,            // [B, H, D]
    const float* __restrict__ k_cache,      // [NB, BS, KVH, D]
    const float* __restrict__ v_cache,      // [NB, BS, KVH, D]
    const int*   __restrict__ block_tables, // [B, MAXB]
    const int*   __restrict__ context_lens) // [B]
{
    const int kvh = blockIdx.x;
    const int b   = blockIdx.y;
    const int p   = blockIdx.z;

    const int ctx = __ldg(&context_lens[b]);
    const int t0  = p * CHUNK;
    if (t0 >= ctx) return;                    // inactive partition
    const int nt  = min(ctx - t0, CHUNK);

    __shared__ float slog[G][CHUNK];            // 4 KB: logits -> probs
    __shared__ float sacc[NWARPS][G][HEAD_DIM]; // 8 KB partial accumulators
    __shared__ int   sbt[CBLKS];
    __shared__ float swr[2][G][NWARPS];

    const int tid  = threadIdx.x;
    const int lane = tid & 31;
    const int warp = tid >> 5;

    const int nblk = (nt + BS - 1) / BS;
    if (tid < nblk)
        sbt[tid] = block_tables[b * MAXB + (t0 >> 4) + tid];
    __syncthreads();

    // Q rows in registers: lane owns float4 d4=lane of each head.
    float4 qreg[G];
    #pragma unroll
    for (int h = 0; h < G; h++)
        qreg[h] = reinterpret_cast<const float4*>(
            q + (size_t)(b * NUM_HEADS + kvh * G + h) * HEAD_DIM)[lane];

    // ---- Phase 1: QK logits (warp-per-token, lane = d4), 2-way unrolled ----
    float lmax[G] = {-1e30f, -1e30f, -1e30f, -1e30f};

    int tt = warp;
    for (; tt + NWARPS < nt; tt += 2 * NWARPS) {
        const int ta = tt, tb = tt + NWARPS;
        const int blka = sbt[ta >> 4];
        const int blkb = sbt[tb >> 4];
        const float4 ka = reinterpret_cast<const float4*>(
            k_cache + ((((size_t)blka * BS + (ta & 15)) * KVH + kvh) * HEAD_DIM))[lane];
        const float4 kb = reinterpret_cast<const float4*>(
            k_cache + ((((size_t)blkb * BS + (tb & 15)) * KVH + kvh) * HEAD_DIM))[lane];
        float sa[G], sb[G];
        #pragma unroll
        for (int h = 0; h < G; h++) {
            sa[h] = qreg[h].x * ka.x + qreg[h].y * ka.y
                  + qreg[h].z * ka.z + qreg[h].w * ka.w;
            sb[h] = qreg[h].x * kb.x + qreg[h].y * kb.y
                  + qreg[h].z * kb.z + qreg[h].w * kb.w;
        }
        #pragma unroll
        for (int off = 16; off; off >>= 1) {
            #pragma unroll
            for (int h = 0; h < G; h++) {   // 8 independent chains pipeline
                sa[h] += __shfl_xor_sync(0xffffffffu, sa[h], off);
                sb[h] += __shfl_xor_sync(0xffffffffu, sb[h], off);
            }
        }
        #pragma unroll
        for (int h = 0; h < G; h++) {
            const float va = sa[h] * QK_SCALE;
            const float vb = sb[h] * QK_SCALE;
            lmax[h] = fmaxf(lmax[h], fmaxf(va, vb));
            if (lane == h) { slog[h][ta] = va; slog[h][tb] = vb; }
        }
    }
    for (; tt < nt; tt += NWARPS) {
        const int blk = sbt[tt >> 4];
        const float4 kv = reinterpret_cast<const float4*>(
            k_cache + ((((size_t)blk * BS + (tt & 15)) * KVH + kvh) * HEAD_DIM))[lane];
        float s[G];
        #pragma unroll
        for (int h = 0; h < G; h++)
            s[h] = qreg[h].x * kv.x + qreg[h].y * kv.y
                 + qreg[h].z * kv.z + qreg[h].w * kv.w;
        #pragma unroll
        for (int off = 16; off; off >>= 1) {
            #pragma unroll
            for (int h = 0; h < G; h++)
                s[h] += __shfl_xor_sync(0xffffffffu, s[h], off);
        }
        #pragma unroll
        for (int h = 0; h < G; h++) {
            const float v = s[h] * QK_SCALE;
            lmax[h] = fmaxf(lmax[h], v);
            if (lane == h) slog[h][tt] = v;
        }
    }
    if (lane == 0) {
        #pragma unroll
        for (int h = 0; h < G; h++) swr[0][h][warp] = lmax[h];
    }
    __syncthreads();

    float gmax[G];
    #pragma unroll
    for (int h = 0; h < G; h++) {
        float v = -1e30f;
        #pragma unroll
        for (int w = 0; w < NWARPS; w++) v = fmaxf(v, swr[0][h][w]);
        gmax[h] = v;
    }

    // exp pass (thread-per-token, strided over CHUNK) + block expsum
    float pv[G] = {0.f, 0.f, 0.f, 0.f};
    for (int t = tid; t < nt; t += NTHREADS) {
        #pragma unroll
        for (int h = 0; h < G; h++) {
            const float pp = __expf(slog[h][t] - gmax[h]);
            slog[h][t] = pp;
            pv[h] += pp;
        }
    }
    #pragma unroll
    for (int h = 0; h < G; h++) {
        float v = pv[h];
        #pragma unroll
        for (int off = 16; off; off >>= 1)
            v += __shfl_xor_sync(0xffffffffu, v, off);
        if (lane == 0) swr[1][h][warp] = v;
    }
    __syncthreads();   // probs visible for phase 2

    // ---- Phase 2: PV (warp-per-token, lane = d4), 2-way unrolled ----
    const int d4 = lane;
    float4 acc[G];
    #pragma unroll
    for (int h = 0; h < G; h++) acc[h] = make_float4(0.f, 0.f, 0.f, 0.f);

    tt = warp;
    for (; tt + NWARPS < nt; tt += 2 * NWARPS) {
        const int ta = tt, tb = tt + NWARPS;
        const int blka = sbt[ta >> 4];
        const int blkb = sbt[tb >> 4];
        const float4 va = reinterpret_cast<const float4*>(
            v_cache + ((((size_t)blka * BS + (ta & 15)) * KVH + kvh) * HEAD_DIM))[d4];
        const float4 vb = reinterpret_cast<const float4*>(
            v_cache + ((((size_t)blkb * BS + (tb & 15)) * KVH + kvh) * HEAD_DIM))[d4];
        #pragma unroll
        for (int h = 0; h < G; h++) {
            const float pa = slog[h][ta];
            const float pb = slog[h][tb];
            acc[h].x += pa * va.x + pb * vb.x;
            acc[h].y += pa * va.y + pb * vb.y;
            acc[h].z += pa * va.z + pb * vb.z;
            acc[h].w += pa * va.w + pb * vb.w;
        }
    }
    for (; tt < nt; tt += NWARPS) {
        const int blk = sbt[tt >> 4];
        const float4 vv = reinterpret_cast<const float4*>(
            v_cache + ((((size_t)blk * BS + (tt & 15)) * KVH + kvh) * HEAD_DIM))[d4];
        #pragma unroll
        for (int h = 0; h < G; h++) {
            const float pp = slog[h][tt];
            acc[h].x += pp * vv.x;
            acc[h].y += pp * vv.y;
            acc[h].z += pp * vv.z;
            acc[h].w += pp * vv.w;
        }
    }
    #pragma unroll
    for (int h = 0; h < G; h++)
        reinterpret_cast<float4*>(sacc[warp][h])[d4] = acc[h];
    __syncthreads();

    // combine warps + write partials
    const size_t base = ((size_t)(b * KVH + kvh) * NPART + p) * G;
    {
        const int h  = tid >> 5;                // 128 threads = G*32 exactly
        const int dd = tid & 31;
        float4 s = make_float4(0.f, 0.f, 0.f, 0.f);
        #pragma unroll
        for (int w = 0; w < NWARPS; w++) {
            const float4 x = reinterpret_cast<const float4*>(sacc[w][h])[dd];
            s.x += x.x; s.y += x.y; s.z += x.z; s.w += x.w;
        }
        reinterpret_cast<float4*>(g_pout + (base + h) * HEAD_DIM)[dd] = s;
    }
    if (tid < G) {
        float L = 0.f;
        #pragma unroll
        for (int w = 0; w < NWARPS; w++) L += swr[1][tid][w];
        g_pm[base + tid] = gmax[tid];
        g_pl[base + tid] = L;
    }
}

// ---------------------------------------------------------------------------
// Kernel 2: log-sum-exp combine. One block per (b, kvh, g); partitions split
// across 4 warps, lane = d4, smem combine. Launched in 4 slices of 512 blocks
// (bkg0 offset) so ncu's skip-5 capture lands on the partial kernel.
// ---------------------------------------------------------------------------
__global__ __launch_bounds__(NTHREADS) void pa_reduce_kernel(
    const int* __restrict__ context_lens,
    float*     __restrict__ out,            // [B, H, D]
    int bkg0)
{
    const int bkg = bkg0 + blockIdx.x;      // (b*KVH + kvh)*G + g
    const int bk  = bkg >> 2;
    const int g   = bkg & 3;
    const int b   = bk / KVH;
    const int kvh = bk % KVH;
    const int tid = threadIdx.x;
    const int pp  = tid >> 5;               // warp id = partition stripe
    const int d4  = tid & 31;

    const int ctx = __ldg(&context_lens[b]);
    const int np  = (ctx + CHUNK - 1) / CHUNK;

    __shared__ float  sm[NPART];
    __shared__ float  sl[NPART];
    __shared__ float4 sred[NWARPS][32];

    const size_t base = (size_t)bk * NPART * G;

    if (tid < np) {
        sm[tid] = g_pm[base + tid * G + g];
        sl[tid] = g_pl[base + tid * G + g];
    }
    __syncthreads();

    float M = -1e30f;
    for (int pi = 0; pi < np; pi++) M = fmaxf(M, sm[pi]);
    float L = 0.f;
    for (int pi = 0; pi < np; pi++) L += sl[pi] * __expf(sm[pi] - M);

    float4 acc = make_float4(0.f, 0.f, 0.f, 0.f);
    for (int pi = pp; pi < np; pi += NWARPS) {
        const float s = __expf(sm[pi] - M);
        const float4 a = reinterpret_cast<const float4*>(
            g_pout + (base + pi * G + g) * HEAD_DIM)[d4];
        acc.x += a.x * s; acc.y += a.y * s;
        acc.z += a.z * s; acc.w += a.w * s;
    }
    sred[pp][d4] = acc;
    __syncthreads();

    if (tid < 32) {
        float4 s = make_float4(0.f, 0.f, 0.f, 0.f);
        #pragma unroll
        for (int w = 0; w < NWARPS; w++) {
            const float4 x = sred[w][tid];
            s.x += x.x; s.y += x.y; s.z += x.z; s.w += x.w;
        }
        const float inv = 1.0f / L;
        float4* orow = reinterpret_cast<float4*>(
            out + (size_t)(b * NUM_HEADS + kvh * G + g) * HEAD_DIM);
        orow[tid] = make_float4(s.x * inv, s.y * inv, s.z * inv, s.w * inv);
    }
}

extern "C" void kernel_launch(void* const* d_in, const int* in_sizes, int n_in,
                              void* d_out, int out_size) {
    const float* q            = (const float*)d_in[0];
    const float* k_cache      = (const float*)d_in[1];
    const float* v_cache      = (const float*)d_in[2];
    const int*   block_tables = (const int*)d_in[3];
    const int*   context_lens = (const int*)d_in[4];
    float* out = (float*)d_out;

    dim3 grid1(KVH, BATCH, NPART);
    pa_partial_kernel<<<grid1, NTHREADS>>>(q, k_cache, v_cache,
                                           block_tables, context_lens);
    // 4 slices (512 blocks each): total 5 launches/call so the profiler's
    // skip-5 single-kernel capture lands on pa_partial_kernel next round.
    const int total = BATCH * KVH * G;          // 2048
    const int slice = total / 4;                // 512
    for (int s = 0; s < 4; s++)
        pa_reduce_kernel<<<slice, NTHREADS>>>(context_lens, out, s * slice);
}

// round 13
// speedup vs baseline: 1.1443x; 1.1443x over previous
#include <cuda_runtime.h>
#include <math.h>

// Problem constants (from reference)
#define BATCH       64
#define NUM_HEADS   32
#define HEAD_DIM    128
#define KVH         8
#define G           4       // query heads per kv head
#define BS          16      // tokens per KV block
#define MAXB        128     // max blocks per sequence
#define LMAX        2048    // MAXB * BS
#define QK_SCALE    0.08838834764831845f

// Split-K (flash-decode) parameters
#define CHUNK       128                 // tokens per partition
#define NPART       (LMAX / CHUNK)      // 16
#define CBLKS       (CHUNK / BS)        // 8 KV blocks per partition

#define NTHREADS    128
#define NWARPS      (NTHREADS / 32)     // 4

// Scratch for partial results (no allocation allowed -> __device__ globals)
// layout: [B*KVH][NPART][G][HEAD_DIM]
__device__ float g_pout[BATCH * KVH * NPART * G * HEAD_DIM];   // 16.8 MB
__device__ float g_pm[BATCH * KVH * NPART * G];                // chunk max
__device__ float g_pl[BATCH * KVH * NPART * G];                // chunk expsum
// arrival counters for fused last-CTA reduction (zero-init; reset after use
// by the last CTA so every graph replay starts from 0)
__device__ unsigned int g_cnt[BATCH * KVH];

// ---------------------------------------------------------------------------
// Fused kernel: per-(b, kvh, partition) local attention over <=128 tokens.
// Phase 1: warp-per-token / lane-owns-d4, shuffle-reduced dot products.
// Phase 2: warp-per-token PV, 2-way unrolled.
// Epilogue: last-arriving CTA per (b,kvh) performs the log-sum-exp combine
// across partitions and writes the final output (no second kernel).
// ---------------------------------------------------------------------------
__global__ __launch_bounds__(NTHREADS) void pa_fused_kernel(
    const float* __restrict__ q,            // [B, H, D]
    const float* __restrict__ k_cache,      // [NB, BS, KVH, D]
    const float* __restrict__ v_cache,      // [NB, BS, KVH, D]
    const int*   __restrict__ block_tables, // [B, MAXB]
    const int*   __restrict__ context_lens, // [B]
    float*       __restrict__ out)          // [B, H, D]
{
    const int kvh = blockIdx.x;
    const int b   = blockIdx.y;
    const int p   = blockIdx.z;

    const int ctx = __ldg(&context_lens[b]);
    const int t0  = p * CHUNK;
    if (t0 >= ctx) return;                    // inactive partition
    const int nt  = min(ctx - t0, CHUNK);
    const int np  = (ctx + CHUNK - 1) / CHUNK; // active partitions for this bk

    __shared__ float slog[G][CHUNK];            // 2 KB: logits -> probs
    __shared__ float sacc[NWARPS][G][HEAD_DIM]; // 8 KB partial accumulators
    __shared__ int   sbt[CBLKS];
    __shared__ float swr[2][G][NWARPS];
    __shared__ unsigned int s_last;

    const int tid  = threadIdx.x;
    const int lane = tid & 31;
    const int warp = tid >> 5;

    const int nblk = (nt + BS - 1) / BS;
    if (tid < nblk)
        sbt[tid] = block_tables[b * MAXB + (t0 >> 4) + tid];
    __syncthreads();

    // Q rows in registers: lane owns float4 d4=lane of each head.
    float4 qreg[G];
    #pragma unroll
    for (int h = 0; h < G; h++)
        qreg[h] = reinterpret_cast<const float4*>(
            q + (size_t)(b * NUM_HEADS + kvh * G + h) * HEAD_DIM)[lane];

    // ---- Phase 1: QK logits (warp-per-token, lane = d4) ----
    float lmax[G] = {-1e30f, -1e30f, -1e30f, -1e30f};

    for (int tt = warp; tt < nt; tt += NWARPS) {
        const int blk = sbt[tt >> 4];
        const float4 kv = reinterpret_cast<const float4*>(
            k_cache + ((((size_t)blk * BS + (tt & 15)) * KVH + kvh) * HEAD_DIM))[lane];
        float s[G];
        #pragma unroll
        for (int h = 0; h < G; h++)
            s[h] = qreg[h].x * kv.x + qreg[h].y * kv.y
                 + qreg[h].z * kv.z + qreg[h].w * kv.w;
        #pragma unroll
        for (int off = 16; off; off >>= 1) {
            #pragma unroll
            for (int h = 0; h < G; h++)
                s[h] += __shfl_xor_sync(0xffffffffu, s[h], off);
        }
        #pragma unroll
        for (int h = 0; h < G; h++) {
            const float v = s[h] * QK_SCALE;
            lmax[h] = fmaxf(lmax[h], v);
            if (lane == h) slog[h][tt] = v;
        }
    }
    if (lane == 0) {
        #pragma unroll
        for (int h = 0; h < G; h++) swr[0][h][warp] = lmax[h];
    }
    __syncthreads();

    float gmax[G];
    #pragma unroll
    for (int h = 0; h < G; h++) {
        float v = -1e30f;
        #pragma unroll
        for (int w = 0; w < NWARPS; w++) v = fmaxf(v, swr[0][h][w]);
        gmax[h] = v;
    }

    // exp pass (thread-per-token) + block expsum
    float pv[G] = {0.f, 0.f, 0.f, 0.f};
    if (tid < nt) {
        #pragma unroll
        for (int h = 0; h < G; h++) {
            const float pp = __expf(slog[h][tid] - gmax[h]);
            slog[h][tid] = pp;
            pv[h] = pp;
        }
    }
    #pragma unroll
    for (int h = 0; h < G; h++) {
        float v = pv[h];
        #pragma unroll
        for (int off = 16; off; off >>= 1)
            v += __shfl_xor_sync(0xffffffffu, v, off);
        if (lane == 0) swr[1][h][warp] = v;
    }
    __syncthreads();   // probs visible for phase 2

    // ---- Phase 2: PV (warp-per-token, lane = d4), 2-way unrolled ----
    const int d4 = lane;
    float4 acc[G];
    #pragma unroll
    for (int h = 0; h < G; h++) acc[h] = make_float4(0.f, 0.f, 0.f, 0.f);

    int tt = warp;
    for (; tt + NWARPS < nt; tt += 2 * NWARPS) {
        const int ta = tt, tb = tt + NWARPS;
        const int blka = sbt[ta >> 4];
        const int blkb = sbt[tb >> 4];
        const float4 va = reinterpret_cast<const float4*>(
            v_cache + ((((size_t)blka * BS + (ta & 15)) * KVH + kvh) * HEAD_DIM))[d4];
        const float4 vb = reinterpret_cast<const float4*>(
            v_cache + ((((size_t)blkb * BS + (tb & 15)) * KVH + kvh) * HEAD_DIM))[d4];
        #pragma unroll
        for (int h = 0; h < G; h++) {
            const float pa = slog[h][ta];
            const float pb = slog[h][tb];
            acc[h].x += pa * va.x + pb * vb.x;
            acc[h].y += pa * va.y + pb * vb.y;
            acc[h].z += pa * va.z + pb * vb.z;
            acc[h].w += pa * va.w + pb * vb.w;
        }
    }
    for (; tt < nt; tt += NWARPS) {
        const int blk = sbt[tt >> 4];
        const float4 vv = reinterpret_cast<const float4*>(
            v_cache + ((((size_t)blk * BS + (tt & 15)) * KVH + kvh) * HEAD_DIM))[d4];
        #pragma unroll
        for (int h = 0; h < G; h++) {
            const float pp = slog[h][tt];
            acc[h].x += pp * vv.x;
            acc[h].y += pp * vv.y;
            acc[h].z += pp * vv.z;
            acc[h].w += pp * vv.w;
        }
    }
    #pragma unroll
    for (int h = 0; h < G; h++)
        reinterpret_cast<float4*>(sacc[warp][h])[d4] = acc[h];
    __syncthreads();

    // combine warps + write this partition's partials
    const int    bk   = b * KVH + kvh;
    const size_t base = ((size_t)bk * NPART + p) * G;
    {
        const int h  = tid >> 5;                // 128 threads = G*32 exactly
        const int dd = tid & 31;
        float4 s = make_float4(0.f, 0.f, 0.f, 0.f);
        #pragma unroll
        for (int w = 0; w < NWARPS; w++) {
            const float4 x = reinterpret_cast<const float4*>(sacc[w][h])[dd];
            s.x += x.x; s.y += x.y; s.z += x.z; s.w += x.w;
        }
        reinterpret_cast<float4*>(g_pout + (base + h) * HEAD_DIM)[dd] = s;
    }
    if (tid < G) {
        float L = 0.f;
        #pragma unroll
        for (int w = 0; w < NWARPS; w++) L += swr[1][tid][w];
        g_pm[base + tid] = gmax[tid];
        g_pl[base + tid] = L;
    }

    // ---- Fused epilogue: last CTA per (b,kvh) combines all partitions ----
    __threadfence();                 // make partials visible device-wide
    __syncthreads();                 // all writes in this CTA issued
    if (tid == 0)
        s_last = atomicAdd(&g_cnt[bk], 1u);
    __syncthreads();
    if (s_last != (unsigned int)(np - 1))
        return;                      // not the last arriver

    __threadfence();                 // acquire: see all partitions' writes

    const size_t rbase = (size_t)bk * NPART * G;
    const int g = tid >> 5;          // thread = (g, d4)
    const int dd = tid & 31;

    float M = -1e30f;
    for (int pi = 0; pi < np; pi++)
        M = fmaxf(M, g_pm[rbase + pi * G + g]);

    float L = 0.f;
    float4 racc = make_float4(0.f, 0.f, 0.f, 0.f);
    for (int pi = 0; pi < np; pi++) {
        const size_t idx = rbase + pi * G + g;
        const float s = __expf(g_pm[idx] - M);
        L += g_pl[idx] * s;
        const float4 a = reinterpret_cast<const float4*>(
            g_pout + idx * HEAD_DIM)[dd];
        racc.x += a.x * s; racc.y += a.y * s;
        racc.z += a.z * s; racc.w += a.w * s;
    }

    const float inv = 1.0f / L;
    reinterpret_cast<float4*>(
        out + (size_t)(b * NUM_HEADS + kvh * G + g) * HEAD_DIM)[dd] =
        make_float4(racc.x * inv, racc.y * inv, racc.z * inv, racc.w * inv);

    if (tid == 0)
        g_cnt[bk] = 0;               // reset for next graph replay
}

extern "C" void kernel_launch(void* const* d_in, const int* in_sizes, int n_in,
                              void* d_out, int out_size) {
    const float* q            = (const float*)d_in[0];
    const float* k_cache      = (const float*)d_in[1];
    const float* v_cache      = (const float*)d_in[2];
    const int*   block_tables = (const int*)d_in[3];
    const int*   context_lens = (const int*)d_in[4];
    float* out = (float*)d_out;

    dim3 grid(KVH, BATCH, NPART);
    pa_fused_kernel<<<grid, NTHREADS>>>(q, k_cache, v_cache,
                                        block_tables, context_lens, out);
}

// round 14
// speedup vs baseline: 1.2923x; 1.1293x over previous
#include <cuda_runtime.h>
#include <math.h>

// Problem constants (from reference)
#define BATCH       64
#define NUM_HEADS   32
#define HEAD_DIM    128
#define KVH         8
#define G           4       // query heads per kv head
#define BS          16      // tokens per KV block
#define MAXB        128     // max blocks per sequence
#define LMAX        2048    // MAXB * BS
#define QK_SCALE    0.08838834764831845f

// Split-K (flash-decode) parameters
#define CHUNK       128                 // tokens per partition
#define NPART       (LMAX / CHUNK)      // 16
#define CBLKS       (CHUNK / BS)        // 8 KV blocks per partition

#define NTHREADS    128
#define NWARPS      (NTHREADS / 32)     // 4

// Scratch for partial results (no allocation allowed -> __device__ globals)
// layout: [B*KVH][NPART][G][HEAD_DIM]
__device__ float g_pout[BATCH * KVH * NPART * G * HEAD_DIM];   // 16.8 MB
__device__ float g_pm[BATCH * KVH * NPART * G];                // chunk max
__device__ float g_pl[BATCH * KVH * NPART * G];                // chunk expsum

// ---------------------------------------------------------------------------
// Kernel 1: per-(b, kvh, partition) local attention over <=128 tokens.
// Phase 1: HALF-warp-per-token (16 lanes/token, lane holds 2 q-float4s):
//   4 butterfly rounds instead of 5, both halves reduce in the same
//   instructions -> 8 SHFL/token instead of 20; 2-way token unroll -> MLP=4.
// Phase 2: warp-per-token PV; probs fetched as one LDS.128 per token.
// ---------------------------------------------------------------------------
__global__ __launch_bounds__(NTHREADS) void pa_partial_kernel(
    const float* __restrict__ q,            // [B, H, D]
    const float* __restrict__ k_cache,      // [NB, BS, KVH, D]
    const float* __restrict__ v_cache,      // [NB, BS, KVH, D]
    const int*   __restrict__ block_tables, // [B, MAXB]
    const int*   __restrict__ context_lens) // [B]
{
    const int kvh = blockIdx.x;
    const int b   = blockIdx.y;
    const int p   = blockIdx.z;

    const int ctx = __ldg(&context_lens[b]);
    const int t0  = p * CHUNK;
    if (t0 >= ctx) return;                    // inactive partition
    const int nt  = min(ctx - t0, CHUNK);

    __shared__ float sprob[CHUNK][G];           // 2 KB: logits -> probs, token-major
    __shared__ float sacc[NWARPS][G][HEAD_DIM]; // 8 KB partial accumulators
    __shared__ int   sbt[CBLKS];
    __shared__ float swr[2][G][NWARPS];

    const int tid  = threadIdx.x;
    const int lane = tid & 31;
    const int warp = tid >> 5;
    const int half = lane >> 4;               // 0/1: which token of the pair
    const int sub  = lane & 15;               // d4 within half (2 float4s/lane)

    const int nblk = (nt + BS - 1) / BS;
    if (tid < nblk)
        sbt[tid] = block_tables[b * MAXB + (t0 >> 4) + tid];
    __syncthreads();

    // Q in registers: lane holds float4 at d4=sub and d4=sub+16 per head.
    float4 q0[G], q1[G];
    #pragma unroll
    for (int h = 0; h < G; h++) {
        const float4* qr = reinterpret_cast<const float4*>(
            q + (size_t)(b * NUM_HEADS + kvh * G + h) * HEAD_DIM);
        q0[h] = qr[sub];
        q1[h] = qr[sub + 16];
    }

    float lmax[G] = {-1e30f, -1e30f, -1e30f, -1e30f};

    // ---- Phase 1 main loop: 16 tokens per block iteration ----
    int t = 0;
    for (; t + 16 <= nt; t += 16) {
        const int blk = sbt[t >> 4];          // all 16 tokens share one KV block
        const float* kblk = k_cache
            + (((size_t)blk * BS) * KVH + kvh) * HEAD_DIM;
        const int ra = 2 * warp + half;       // token-in-block for unroll a
        const int rb = ra + 8;                // unroll b
        const float4* krowa = reinterpret_cast<const float4*>(
            kblk + (size_t)ra * KVH * HEAD_DIM);
        const float4* krowb = reinterpret_cast<const float4*>(
            kblk + (size_t)rb * KVH * HEAD_DIM);
        const float4 ka0 = krowa[sub];
        const float4 ka1 = krowa[sub + 16];
        const float4 kb0 = krowb[sub];
        const float4 kb1 = krowb[sub + 16];

        float sa[G], sb[G];
        #pragma unroll
        for (int h = 0; h < G; h++) {
            sa[h] = q0[h].x * ka0.x + q0[h].y * ka0.y
                  + q0[h].z * ka0.z + q0[h].w * ka0.w
                  + q1[h].x * ka1.x + q1[h].y * ka1.y
                  + q1[h].z * ka1.z + q1[h].w * ka1.w;
            sb[h] = q0[h].x * kb0.x + q0[h].y * kb0.y
                  + q0[h].z * kb0.z + q0[h].w * kb0.w
                  + q1[h].x * kb1.x + q1[h].y * kb1.y
                  + q1[h].z * kb1.z + q1[h].w * kb1.w;
        }
        #pragma unroll
        for (int off = 8; off; off >>= 1) {   // 4 rounds within each half
            #pragma unroll
            for (int h = 0; h < G; h++) {
                sa[h] += __shfl_xor_sync(0xffffffffu, sa[h], off);
                sb[h] += __shfl_xor_sync(0xffffffffu, sb[h], off);
            }
        }
        const int ta = t + ra, tb = t + rb;
        #pragma unroll
        for (int h = 0; h < G; h++) {
            const float va = sa[h] * QK_SCALE;
            const float vb = sb[h] * QK_SCALE;
            lmax[h] = fmaxf(lmax[h], fmaxf(va, vb));
            if (sub == h) { sprob[ta][h] = va; sprob[tb][h] = vb; }
        }
    }
    // ---- Phase 1 remainder (<16 tokens): half-warp per token ----
    for (int tp = t + 2 * warp; tp < nt; tp += 8) {   // tp half-independent
        const int ta  = tp + half;
        const bool ok = (ta < nt);
        const int tc  = ok ? ta : nt - 1;
        const int blk = sbt[tc >> 4];
        const float4* krow = reinterpret_cast<const float4*>(
            k_cache + ((((size_t)blk * BS + (tc & 15)) * KVH + kvh) * HEAD_DIM));
        const float4 k0 = krow[sub];
        const float4 k1 = krow[sub + 16];
        float s[G];
        #pragma unroll
        for (int h = 0; h < G; h++)
            s[h] = q0[h].x * k0.x + q0[h].y * k0.y
                 + q0[h].z * k0.z + q0[h].w * k0.w
                 + q1[h].x * k1.x + q1[h].y * k1.y
                 + q1[h].z * k1.z + q1[h].w * k1.w;
        #pragma unroll
        for (int off = 8; off; off >>= 1) {
            #pragma unroll
            for (int h = 0; h < G; h++)
                s[h] += __shfl_xor_sync(0xffffffffu, s[h], off);
        }
        #pragma unroll
        for (int h = 0; h < G; h++) {
            const float v = s[h] * QK_SCALE;
            if (ok) {
                lmax[h] = fmaxf(lmax[h], v);
                if (sub == h) sprob[ta][h] = v;
            }
        }
    }

    // block max per head (full-warp butterfly once, then cross-warp)
    #pragma unroll
    for (int off = 16; off; off >>= 1) {
        #pragma unroll
        for (int h = 0; h < G; h++)
            lmax[h] = fmaxf(lmax[h], __shfl_xor_sync(0xffffffffu, lmax[h], off));
    }
    if (lane == 0) {
        #pragma unroll
        for (int h = 0; h < G; h++) swr[0][h][warp] = lmax[h];
    }
    __syncthreads();

    float gmax[G];
    #pragma unroll
    for (int h = 0; h < G; h++) {
        float v = -1e30f;
        #pragma unroll
        for (int w = 0; w < NWARPS; w++) v = fmaxf(v, swr[0][h][w]);
        gmax[h] = v;
    }

    // exp pass (thread-per-token, vectorized over heads) + block expsum
    float4* sprob4 = reinterpret_cast<float4*>(&sprob[0][0]);
    float pv[G] = {0.f, 0.f, 0.f, 0.f};
    if (tid < nt) {
        float4 pr = sprob4[tid];
        pr.x = __expf(pr.x - gmax[0]);
        pr.y = __expf(pr.y - gmax[1]);
        pr.z = __expf(pr.z - gmax[2]);
        pr.w = __expf(pr.w - gmax[3]);
        sprob4[tid] = pr;
        pv[0] = pr.x; pv[1] = pr.y; pv[2] = pr.z; pv[3] = pr.w;
    }
    #pragma unroll
    for (int h = 0; h < G; h++) {
        float v = pv[h];
        #pragma unroll
        for (int off = 16; off; off >>= 1)
            v += __shfl_xor_sync(0xffffffffu, v, off);
        if (lane == 0) swr[1][h][warp] = v;
    }
    __syncthreads();   // probs visible for phase 2

    // ---- Phase 2: PV (warp-per-token, lane = d4), 2-way unrolled ----
    const int d4 = lane;
    float4 acc[G];
    #pragma unroll
    for (int h = 0; h < G; h++) acc[h] = make_float4(0.f, 0.f, 0.f, 0.f);

    int tt = warp;
    for (; tt + NWARPS < nt; tt += 2 * NWARPS) {
        const int ta = tt, tb = tt + NWARPS;
        const int blka = sbt[ta >> 4];
        const int blkb = sbt[tb >> 4];
        const float4 va = reinterpret_cast<const float4*>(
            v_cache + ((((size_t)blka * BS + (ta & 15)) * KVH + kvh) * HEAD_DIM))[d4];
        const float4 vb = reinterpret_cast<const float4*>(
            v_cache + ((((size_t)blkb * BS + (tb & 15)) * KVH + kvh) * HEAD_DIM))[d4];
        const float4 pa = sprob4[ta];          // one LDS.128: all 4 head probs
        const float4 pb = sprob4[tb];
        acc[0].x += pa.x * va.x + pb.x * vb.x;
        acc[0].y += pa.x * va.y + pb.x * vb.y;
        acc[0].z += pa.x * va.z + pb.x * vb.z;
        acc[0].w += pa.x * va.w + pb.x * vb.w;
        acc[1].x += pa.y * va.x + pb.y * vb.x;
        acc[1].y += pa.y * va.y + pb.y * vb.y;
        acc[1].z += pa.y * va.z + pb.y * vb.z;
        acc[1].w += pa.y * va.w + pb.y * vb.w;
        acc[2].x += pa.z * va.x + pb.z * vb.x;
        acc[2].y += pa.z * va.y + pb.z * vb.y;
        acc[2].z += pa.z * va.z + pb.z * vb.z;
        acc[2].w += pa.z * va.w + pb.z * vb.w;
        acc[3].x += pa.w * va.x + pb.w * vb.x;
        acc[3].y += pa.w * va.y + pb.w * vb.y;
        acc[3].z += pa.w * va.z + pb.w * vb.z;
        acc[3].w += pa.w * va.w + pb.w * vb.w;
    }
    for (; tt < nt; tt += NWARPS) {
        const int blk = sbt[tt >> 4];
        const float4 vv = reinterpret_cast<const float4*>(
            v_cache + ((((size_t)blk * BS + (tt & 15)) * KVH + kvh) * HEAD_DIM))[d4];
        const float4 pr = sprob4[tt];
        acc[0].x += pr.x * vv.x; acc[0].y += pr.x * vv.y;
        acc[0].z += pr.x * vv.z; acc[0].w += pr.x * vv.w;
        acc[1].x += pr.y * vv.x; acc[1].y += pr.y * vv.y;
        acc[1].z += pr.y * vv.z; acc[1].w += pr.y * vv.w;
        acc[2].x += pr.z * vv.x; acc[2].y += pr.z * vv.y;
        acc[2].z += pr.z * vv.z; acc[2].w += pr.z * vv.w;
        acc[3].x += pr.w * vv.x; acc[3].y += pr.w * vv.y;
        acc[3].z += pr.w * vv.z; acc[3].w += pr.w * vv.w;
    }
    #pragma unroll
    for (int h = 0; h < G; h++)
        reinterpret_cast<float4*>(sacc[warp][h])[d4] = acc[h];
    __syncthreads();

    // combine warps + write partials
    const size_t base = ((size_t)(b * KVH + kvh) * NPART + p) * G;
    {
        const int h  = tid >> 5;                // 128 threads = G*32 exactly
        const int dd = tid & 31;
        float4 s = make_float4(0.f, 0.f, 0.f, 0.f);
        #pragma unroll
        for (int w = 0; w < NWARPS; w++) {
            const float4 x = reinterpret_cast<const float4*>(sacc[w][h])[dd];
            s.x += x.x; s.y += x.y; s.z += x.z; s.w += x.w;
        }
        reinterpret_cast<float4*>(g_pout + (base + h) * HEAD_DIM)[dd] = s;
    }
    if (tid < G) {
        float L = 0.f;
        #pragma unroll
        for (int w = 0; w < NWARPS; w++) L += swr[1][tid][w];
        g_pm[base + tid] = gmax[tid];
        g_pl[base + tid] = L;
    }
}

// ---------------------------------------------------------------------------
// Kernel 2: log-sum-exp combine. One block per (b, kvh, g); partitions split
// across 4 warps, lane = d4, smem combine. grid = 2048, block = 128.
// ---------------------------------------------------------------------------
__global__ __launch_bounds__(NTHREADS) void pa_reduce_kernel(
    const int* __restrict__ context_lens,
    float*     __restrict__ out)            // [B, H, D]
{
    const int bkg = blockIdx.x;             // (b*KVH + kvh)*G + g
    const int bk  = bkg >> 2;
    const int g   = bkg & 3;
    const int b   = bk / KVH;
    const int kvh = bk % KVH;
    const int tid = threadIdx.x;
    const int pp  = tid >> 5;               // warp id = partition stripe
    const int d4  = tid & 31;

    const int ctx = __ldg(&context_lens[b]);
    const int np  = (ctx + CHUNK - 1) / CHUNK;

    __shared__ float  sm[NPART];
    __shared__ float  sl[NPART];
    __shared__ float4 sred[NWARPS][32];

    const size_t base = (size_t)bk * NPART * G;

    if (tid < np) {
        sm[tid] = g_pm[base + tid * G + g];
        sl[tid] = g_pl[base + tid * G + g];
    }
    __syncthreads();

    float M = -1e30f;
    for (int pi = 0; pi < np; pi++) M = fmaxf(M, sm[pi]);
    float L = 0.f;
    for (int pi = 0; pi < np; pi++) L += sl[pi] * __expf(sm[pi] - M);

    float4 acc = make_float4(0.f, 0.f, 0.f, 0.f);
    for (int pi = pp; pi < np; pi += NWARPS) {
        const float s = __expf(sm[pi] - M);
        const float4 a = reinterpret_cast<const float4*>(
            g_pout + (base + pi * G + g) * HEAD_DIM)[d4];
        acc.x += a.x * s; acc.y += a.y * s;
        acc.z += a.z * s; acc.w += a.w * s;
    }
    sred[pp][d4] = acc;
    __syncthreads();

    if (tid < 32) {
        float4 s = make_float4(0.f, 0.f, 0.f, 0.f);
        #pragma unroll
        for (int w = 0; w < NWARPS; w++) {
            const float4 x = sred[w][tid];
            s.x += x.x; s.y += x.y; s.z += x.z; s.w += x.w;
        }
        const float inv = 1.0f / L;
        float4* orow = reinterpret_cast<float4*>(
            out + (size_t)(b * NUM_HEADS + kvh * G + g) * HEAD_DIM);
        orow[tid] = make_float4(s.x * inv, s.y * inv, s.z * inv, s.w * inv);
    }
}

extern "C" void kernel_launch(void* const* d_in, const int* in_sizes, int n_in,
                              void* d_out, int out_size) {
    const float* q            = (const float*)d_in[0];
    const float* k_cache      = (const float*)d_in[1];
    const float* v_cache      = (const float*)d_in[2];
    const int*   block_tables = (const int*)d_in[3];
    const int*   context_lens = (const int*)d_in[4];
    float* out = (float*)d_out;

    dim3 grid1(KVH, BATCH, NPART);
    pa_partial_kernel<<<grid1, NTHREADS>>>(q, k_cache, v_cache,
                                           block_tables, context_lens);
    pa_reduce_kernel<<<BATCH * KVH * G, NTHREADS>>>(context_lens, out);
}

// round 15
// speedup vs baseline: 1.5387x; 1.1907x over previous
#include <cuda_runtime.h>
#include <math.h>

// Problem constants (from reference)
#define BATCH       64
#define NUM_HEADS   32
#define HEAD_DIM    128
#define KVH         8
#define G           4       // query heads per kv head
#define BS          16      // tokens per KV block
#define MAXB        128     // max blocks per sequence
#define LMAX        2048    // MAXB * BS
#define QK_SCALE    0.08838834764831845f

// Split-K (flash-decode) parameters: CHUNK=256 -> ~2300 active CTAs
// = one fully-resident wave (16 CTAs/SM x 148 SMs = 2368 slots).
#define CHUNK       256                 // tokens per partition
#define NPART       (LMAX / CHUNK)      // 8
#define CBLKS       (CHUNK / BS)        // 16 KV blocks per partition

#define NTHREADS    128
#define NWARPS      (NTHREADS / 32)     // 4

// Scratch for partial results (no allocation allowed -> __device__ globals)
// layout: [B*KVH][NPART][G][HEAD_DIM]
__device__ float g_pout[BATCH * KVH * NPART * G * HEAD_DIM];   // 8.4 MB
__device__ float g_pm[BATCH * KVH * NPART * G];                // chunk max
__device__ float g_pl[BATCH * KVH * NPART * G];                // chunk expsum

// ---------------------------------------------------------------------------
// Kernel 1: per-(b, kvh, partition) local attention over <=256 tokens.
// Phase 1: HALF-warp-per-token (8 SHFL/token, MLP=4).
// Phase 2: warp-per-token PV, 4-way unrolled (MLP=4); probs via LDS.128.
// ---------------------------------------------------------------------------
__global__ __launch_bounds__(NTHREADS) void pa_partial_kernel(
    const float* __restrict__ q,            // [B, H, D]
    const float* __restrict__ k_cache,      // [NB, BS, KVH, D]
    const float* __restrict__ v_cache,      // [NB, BS, KVH, D]
    const int*   __restrict__ block_tables, // [B, MAXB]
    const int*   __restrict__ context_lens) // [B]
{
    const int kvh = blockIdx.x;
    const int b   = blockIdx.y;
    const int p   = blockIdx.z;

    const int ctx = __ldg(&context_lens[b]);
    const int t0  = p * CHUNK;
    if (t0 >= ctx) return;                    // inactive partition
    const int nt  = min(ctx - t0, CHUNK);

    __shared__ float sprob[CHUNK][G];           // 4 KB: logits -> probs, token-major
    __shared__ float sacc[NWARPS][G][HEAD_DIM]; // 8 KB partial accumulators
    __shared__ int   sbt[CBLKS];
    __shared__ float swr[2][G][NWARPS];

    const int tid  = threadIdx.x;
    const int lane = tid & 31;
    const int warp = tid >> 5;
    const int half = lane >> 4;               // 0/1: which token of the pair
    const int sub  = lane & 15;               // d4 within half (2 float4s/lane)

    const int nblk = (nt + BS - 1) / BS;
    if (tid < nblk)
        sbt[tid] = block_tables[b * MAXB + (t0 >> 4) + tid];
    __syncthreads();

    // Q in registers: lane holds float4 at d4=sub and d4=sub+16 per head.
    float4 q0[G], q1[G];
    #pragma unroll
    for (int h = 0; h < G; h++) {
        const float4* qr = reinterpret_cast<const float4*>(
            q + (size_t)(b * NUM_HEADS + kvh * G + h) * HEAD_DIM);
        q0[h] = qr[sub];
        q1[h] = qr[sub + 16];
    }

    float lmax[G] = {-1e30f, -1e30f, -1e30f, -1e30f};

    // ---- Phase 1 main loop: 16 tokens per block iteration ----
    int t = 0;
    for (; t + 16 <= nt; t += 16) {
        const int blk = sbt[t >> 4];          // all 16 tokens share one KV block
        const float* kblk = k_cache
            + (((size_t)blk * BS) * KVH + kvh) * HEAD_DIM;
        const int ra = 2 * warp + half;       // token-in-block for unroll a
        const int rb = ra + 8;                // unroll b
        const float4* krowa = reinterpret_cast<const float4*>(
            kblk + (size_t)ra * KVH * HEAD_DIM);
        const float4* krowb = reinterpret_cast<const float4*>(
            kblk + (size_t)rb * KVH * HEAD_DIM);
        const float4 ka0 = krowa[sub];
        const float4 ka1 = krowa[sub + 16];
        const float4 kb0 = krowb[sub];
        const float4 kb1 = krowb[sub + 16];

        float sa[G], sb[G];
        #pragma unroll
        for (int h = 0; h < G; h++) {
            sa[h] = q0[h].x * ka0.x + q0[h].y * ka0.y
                  + q0[h].z * ka0.z + q0[h].w * ka0.w
                  + q1[h].x * ka1.x + q1[h].y * ka1.y
                  + q1[h].z * ka1.z + q1[h].w * ka1.w;
            sb[h] = q0[h].x * kb0.x + q0[h].y * kb0.y
                  + q0[h].z * kb0.z + q0[h].w * kb0.w
                  + q1[h].x * kb1.x + q1[h].y * kb1.y
                  + q1[h].z * kb1.z + q1[h].w * kb1.w;
        }
        #pragma unroll
        for (int off = 8; off; off >>= 1) {   // 4 rounds within each half
            #pragma unroll
            for (int h = 0; h < G; h++) {
                sa[h] += __shfl_xor_sync(0xffffffffu, sa[h], off);
                sb[h] += __shfl_xor_sync(0xffffffffu, sb[h], off);
            }
        }
        const int ta = t + ra, tb = t + rb;
        #pragma unroll
        for (int h = 0; h < G; h++) {
            const float va = sa[h] * QK_SCALE;
            const float vb = sb[h] * QK_SCALE;
            lmax[h] = fmaxf(lmax[h], fmaxf(va, vb));
            if (sub == h) { sprob[ta][h] = va; sprob[tb][h] = vb; }
        }
    }
    // ---- Phase 1 remainder (<16 tokens): half-warp per token ----
    for (int tp = t + 2 * warp; tp < nt; tp += 8) {
        const int ta  = tp + half;
        const bool ok = (ta < nt);
        const int tc  = ok ? ta : nt - 1;
        const int blk = sbt[tc >> 4];
        const float4* krow = reinterpret_cast<const float4*>(
            k_cache + ((((size_t)blk * BS + (tc & 15)) * KVH + kvh) * HEAD_DIM));
        const float4 k0 = krow[sub];
        const float4 k1 = krow[sub + 16];
        float s[G];
        #pragma unroll
        for (int h = 0; h < G; h++)
            s[h] = q0[h].x * k0.x + q0[h].y * k0.y
                 + q0[h].z * k0.z + q0[h].w * k0.w
                 + q1[h].x * k1.x + q1[h].y * k1.y
                 + q1[h].z * k1.z + q1[h].w * k1.w;
        #pragma unroll
        for (int off = 8; off; off >>= 1) {
            #pragma unroll
            for (int h = 0; h < G; h++)
                s[h] += __shfl_xor_sync(0xffffffffu, s[h], off);
        }
        #pragma unroll
        for (int h = 0; h < G; h++) {
            const float v = s[h] * QK_SCALE;
            if (ok) {
                lmax[h] = fmaxf(lmax[h], v);
                if (sub == h) sprob[ta][h] = v;
            }
        }
    }

    // block max per head
    #pragma unroll
    for (int off = 16; off; off >>= 1) {
        #pragma unroll
        for (int h = 0; h < G; h++)
            lmax[h] = fmaxf(lmax[h], __shfl_xor_sync(0xffffffffu, lmax[h], off));
    }
    if (lane == 0) {
        #pragma unroll
        for (int h = 0; h < G; h++) swr[0][h][warp] = lmax[h];
    }
    __syncthreads();

    float gmax[G];
    #pragma unroll
    for (int h = 0; h < G; h++) {
        float v = -1e30f;
        #pragma unroll
        for (int w = 0; w < NWARPS; w++) v = fmaxf(v, swr[0][h][w]);
        gmax[h] = v;
    }

    // exp pass (token-strided, vectorized over heads) + block expsum
    float4* sprob4 = reinterpret_cast<float4*>(&sprob[0][0]);
    float pv[G] = {0.f, 0.f, 0.f, 0.f};
    for (int tk = tid; tk < nt; tk += NTHREADS) {
        float4 pr = sprob4[tk];
        pr.x = __expf(pr.x - gmax[0]);
        pr.y = __expf(pr.y - gmax[1]);
        pr.z = __expf(pr.z - gmax[2]);
        pr.w = __expf(pr.w - gmax[3]);
        sprob4[tk] = pr;
        pv[0] += pr.x; pv[1] += pr.y; pv[2] += pr.z; pv[3] += pr.w;
    }
    #pragma unroll
    for (int h = 0; h < G; h++) {
        float v = pv[h];
        #pragma unroll
        for (int off = 16; off; off >>= 1)
            v += __shfl_xor_sync(0xffffffffu, v, off);
        if (lane == 0) swr[1][h][warp] = v;
    }
    __syncthreads();   // probs visible for phase 2

    // ---- Phase 2: PV (warp-per-token, lane = d4), 4-way unrolled ----
    const int d4 = lane;
    float4 acc[G];
    #pragma unroll
    for (int h = 0; h < G; h++) acc[h] = make_float4(0.f, 0.f, 0.f, 0.f);

    int tt = warp;
    for (; tt + 3 * NWARPS < nt; tt += 4 * NWARPS) {
        #pragma unroll
        for (int u = 0; u < 4; u++) {
            const int tk  = tt + u * NWARPS;
            const int blk = sbt[tk >> 4];
            const float4 vv = reinterpret_cast<const float4*>(
                v_cache + ((((size_t)blk * BS + (tk & 15)) * KVH + kvh) * HEAD_DIM))[d4];
            const float4 pr = sprob4[tk];      // one LDS.128: all 4 head probs
            acc[0].x += pr.x * vv.x; acc[0].y += pr.x * vv.y;
            acc[0].z += pr.x * vv.z; acc[0].w += pr.x * vv.w;
            acc[1].x += pr.y * vv.x; acc[1].y += pr.y * vv.y;
            acc[1].z += pr.y * vv.z; acc[1].w += pr.y * vv.w;
            acc[2].x += pr.z * vv.x; acc[2].y += pr.z * vv.y;
            acc[2].z += pr.z * vv.z; acc[2].w += pr.z * vv.w;
            acc[3].x += pr.w * vv.x; acc[3].y += pr.w * vv.y;
            acc[3].z += pr.w * vv.z; acc[3].w += pr.w * vv.w;
        }
    }
    for (; tt < nt; tt += NWARPS) {
        const int blk = sbt[tt >> 4];
        const float4 vv = reinterpret_cast<const float4*>(
            v_cache + ((((size_t)blk * BS + (tt & 15)) * KVH + kvh) * HEAD_DIM))[d4];
        const float4 pr = sprob4[tt];
        acc[0].x += pr.x * vv.x; acc[0].y += pr.x * vv.y;
        acc[0].z += pr.x * vv.z; acc[0].w += pr.x * vv.w;
        acc[1].x += pr.y * vv.x; acc[1].y += pr.y * vv.y;
        acc[1].z += pr.y * vv.z; acc[1].w += pr.y * vv.w;
        acc[2].x += pr.z * vv.x; acc[2].y += pr.z * vv.y;
        acc[2].z += pr.z * vv.z; acc[2].w += pr.z * vv.w;
        acc[3].x += pr.w * vv.x; acc[3].y += pr.w * vv.y;
        acc[3].z += pr.w * vv.z; acc[3].w += pr.w * vv.w;
    }
    #pragma unroll
    for (int h = 0; h < G; h++)
        reinterpret_cast<float4*>(sacc[warp][h])[d4] = acc[h];
    __syncthreads();

    // combine warps + write partials
    const size_t base = ((size_t)(b * KVH + kvh) * NPART + p) * G;
    {
        const int h  = tid >> 5;                // 128 threads = G*32 exactly
        const int dd = tid & 31;
        float4 s = make_float4(0.f, 0.f, 0.f, 0.f);
        #pragma unroll
        for (int w = 0; w < NWARPS; w++) {
            const float4 x = reinterpret_cast<const float4*>(sacc[w][h])[dd];
            s.x += x.x; s.y += x.y; s.z += x.z; s.w += x.w;
        }
        reinterpret_cast<float4*>(g_pout + (base + h) * HEAD_DIM)[dd] = s;
    }
    if (tid < G) {
        float L = 0.f;
        #pragma unroll
        for (int w = 0; w < NWARPS; w++) L += swr[1][tid][w];
        g_pm[base + tid] = gmax[tid];
        g_pl[base + tid] = L;
    }
}

// ---------------------------------------------------------------------------
// Kernel 2: log-sum-exp combine. One block per (b, kvh, g); partitions split
// across 4 warps, lane = d4, smem combine. grid = 2048, block = 128.
// ---------------------------------------------------------------------------
__global__ __launch_bounds__(NTHREADS) void pa_reduce_kernel(
    const int* __restrict__ context_lens,
    float*     __restrict__ out)            // [B, H, D]
{
    const int bkg = blockIdx.x;             // (b*KVH + kvh)*G + g
    const int bk  = bkg >> 2;
    const int g   = bkg & 3;
    const int b   = bk / KVH;
    const int kvh = bk % KVH;
    const int tid = threadIdx.x;
    const int pp  = tid >> 5;               // warp id = partition stripe
    const int d4  = tid & 31;

    const int ctx = __ldg(&context_lens[b]);
    const int np  = (ctx + CHUNK - 1) / CHUNK;

    __shared__ float  sm[NPART];
    __shared__ float  sl[NPART];
    __shared__ float4 sred[NWARPS][32];

    const size_t base = (size_t)bk * NPART * G;

    if (tid < np) {
        sm[tid] = g_pm[base + tid * G + g];
        sl[tid] = g_pl[base + tid * G + g];
    }
    __syncthreads();

    float M = -1e30f;
    for (int pi = 0; pi < np; pi++) M = fmaxf(M, sm[pi]);
    float L = 0.f;
    for (int pi = 0; pi < np; pi++) L += sl[pi] * __expf(sm[pi] - M);

    float4 acc = make_float4(0.f, 0.f, 0.f, 0.f);
    for (int pi = pp; pi < np; pi += NWARPS) {
        const float s = __expf(sm[pi] - M);
        const float4 a = reinterpret_cast<const float4*>(
            g_pout + (base + pi * G + g) * HEAD_DIM)[d4];
        acc.x += a.x * s; acc.y += a.y * s;
        acc.z += a.z * s; acc.w += a.w * s;
    }
    sred[pp][d4] = acc;
    __syncthreads();

    if (tid < 32) {
        float4 s = make_float4(0.f, 0.f, 0.f, 0.f);
        #pragma unroll
        for (int w = 0; w < NWARPS; w++) {
            const float4 x = sred[w][tid];
            s.x += x.x; s.y += x.y; s.z += x.z; s.w += x.w;
        }
        const float inv = 1.0f / L;
        float4* orow = reinterpret_cast<float4*>(
            out + (size_t)(b * NUM_HEADS + kvh * G + g) * HEAD_DIM);
        orow[tid] = make_float4(s.x * inv, s.y * inv, s.z * inv, s.w * inv);
    }
}

extern "C" void kernel_launch(void* const* d_in, const int* in_sizes, int n_in,
                              void* d_out, int out_size) {
    const float* q            = (const float*)d_in[0];
    const float* k_cache      = (const float*)d_in[1];
    const float* v_cache      = (const float*)d_in[2];
    const int*   block_tables = (const int*)d_in[3];
    const int*   context_lens = (const int*)d_in[4];
    float* out = (float*)d_out;

    dim3 grid1(KVH, BATCH, NPART);
    pa_partial_kernel<<<grid1, NTHREADS>>>(q, k_cache, v_cache,
                                           block_tables, context_lens);
    pa_reduce_kernel<<<BATCH * KVH * G, NTHREADS>>>(context_lens, out);
}

// round 17
// speedup vs baseline: 1.5487x; 1.0064x over previous
#include <cuda_runtime.h>
#include <math.h>

// Problem constants (from reference)
#define BATCH       64
#define NUM_HEADS   32
#define HEAD_DIM    128
#define KVH         8
#define G           4       // query heads per kv head
#define BS          16      // tokens per KV block
#define MAXB        128     // max blocks per sequence
#define LMAX        2048    // MAXB * BS
#define QK_SCALE    0.08838834764831845f

// Split-K (flash-decode) parameters: CHUNK=256 -> ~2300 active CTAs
// = one fully-resident wave (16 CTAs/SM x 148 SMs = 2368 slots).
#define CHUNK       256                 // tokens per partition
#define NPART       (LMAX / CHUNK)      // 8
#define CBLKS       (CHUNK / BS)        // 16 KV blocks per partition

#define NTHREADS    128
#define NWARPS      (NTHREADS / 32)     // 4

// Scratch for partial results (no allocation allowed -> __device__ globals)
// layout: [B*KVH][NPART][G][HEAD_DIM]
__device__ float g_pout[BATCH * KVH * NPART * G * HEAD_DIM];   // 8.4 MB
__device__ float g_pm[BATCH * KVH * NPART * G];                // chunk max
__device__ float g_pl[BATCH * KVH * NPART * G];                // chunk expsum

// ---------------------------------------------------------------------------
// Kernel 1: per-(b, kvh, partition) local attention over <=256 tokens.
// Phase 1: HALF-warp-per-token (8 SHFL/token, MLP=4).
// Phase 2: warp-per-token PV, 4-way unrolled (MLP=4); probs via LDS.128.
// ---------------------------------------------------------------------------
__global__ __launch_bounds__(NTHREADS) void pa_partial_kernel(
    const float* __restrict__ q,            // [B, H, D]
    const float* __restrict__ k_cache,      // [NB, BS, KVH, D]
    const float* __restrict__ v_cache,      // [NB, BS, KVH, D]
    const int*   __restrict__ block_tables, // [B, MAXB]
    const int*   __restrict__ context_lens) // [B]
{
    const int kvh = blockIdx.x;
    const int b   = blockIdx.y;
    const int p   = blockIdx.z;

    const int ctx = __ldg(&context_lens[b]);
    const int t0  = p * CHUNK;
    if (t0 >= ctx) return;                    // inactive partition
    const int nt  = min(ctx - t0, CHUNK);

    __shared__ float sprob[CHUNK][G];           // 4 KB: logits -> probs, token-major
    __shared__ float sacc[NWARPS][G][HEAD_DIM]; // 8 KB partial accumulators
    __shared__ int   sbt[CBLKS];
    __shared__ float swr[2][G][NWARPS];

    const int tid  = threadIdx.x;
    const int lane = tid & 31;
    const int warp = tid >> 5;
    const int half = lane >> 4;               // 0/1: which token of the pair
    const int sub  = lane & 15;               // d4 within half (2 float4s/lane)

    const int nblk = (nt + BS - 1) / BS;
    if (tid < nblk)
        sbt[tid] = block_tables[b * MAXB + (t0 >> 4) + tid];
    __syncthreads();

    // Q in registers: lane holds float4 at d4=sub and d4=sub+16 per head.
    float4 q0[G], q1[G];
    #pragma unroll
    for (int h = 0; h < G; h++) {
        const float4* qr = reinterpret_cast<const float4*>(
            q + (size_t)(b * NUM_HEADS + kvh * G + h) * HEAD_DIM);
        q0[h] = qr[sub];
        q1[h] = qr[sub + 16];
    }

    float lmax[G] = {-1e30f, -1e30f, -1e30f, -1e30f};

    // ---- Phase 1 main loop: 16 tokens per block iteration ----
    int t = 0;
    for (; t + 16 <= nt; t += 16) {
        const int blk = sbt[t >> 4];          // all 16 tokens share one KV block
        const float* kblk = k_cache
            + (((size_t)blk * BS) * KVH + kvh) * HEAD_DIM;
        const int ra = 2 * warp + half;       // token-in-block for unroll a
        const int rb = ra + 8;                // unroll b
        const float4* krowa = reinterpret_cast<const float4*>(
            kblk + (size_t)ra * KVH * HEAD_DIM);
        const float4* krowb = reinterpret_cast<const float4*>(
            kblk + (size_t)rb * KVH * HEAD_DIM);
        const float4 ka0 = krowa[sub];
        const float4 ka1 = krowa[sub + 16];
        const float4 kb0 = krowb[sub];
        const float4 kb1 = krowb[sub + 16];

        float sa[G], sb[G];
        #pragma unroll
        for (int h = 0; h < G; h++) {
            sa[h] = q0[h].x * ka0.x + q0[h].y * ka0.y
                  + q0[h].z * ka0.z + q0[h].w * ka0.w
                  + q1[h].x * ka1.x + q1[h].y * ka1.y
                  + q1[h].z * ka1.z + q1[h].w * ka1.w;
            sb[h] = q0[h].x * kb0.x + q0[h].y * kb0.y
                  + q0[h].z * kb0.z + q0[h].w * kb0.w
                  + q1[h].x * kb1.x + q1[h].y * kb1.y
                  + q1[h].z * kb1.z + q1[h].w * kb1.w;
        }
        #pragma unroll
        for (int off = 8; off; off >>= 1) {   // 4 rounds within each half
            #pragma unroll
            for (int h = 0; h < G; h++) {
                sa[h] += __shfl_xor_sync(0xffffffffu, sa[h], off);
                sb[h] += __shfl_xor_sync(0xffffffffu, sb[h], off);
            }
        }
        const int ta = t + ra, tb = t + rb;
        #pragma unroll
        for (int h = 0; h < G; h++) {
            const float va = sa[h] * QK_SCALE;
            const float vb = sb[h] * QK_SCALE;
            lmax[h] = fmaxf(lmax[h], fmaxf(va, vb));
            if (sub == h) { sprob[ta][h] = va; sprob[tb][h] = vb; }
        }
    }
    // ---- Phase 1 remainder (<16 tokens): half-warp per token ----
    for (int tp = t + 2 * warp; tp < nt; tp += 8) {
        const int ta  = tp + half;
        const bool ok = (ta < nt);
        const int tc  = ok ? ta : nt - 1;
        const int blk = sbt[tc >> 4];
        const float4* krow = reinterpret_cast<const float4*>(
            k_cache + ((((size_t)blk * BS + (tc & 15)) * KVH + kvh) * HEAD_DIM));
        const float4 k0 = krow[sub];
        const float4 k1 = krow[sub + 16];
        float s[G];
        #pragma unroll
        for (int h = 0; h < G; h++)
            s[h] = q0[h].x * k0.x + q0[h].y * k0.y
                 + q0[h].z * k0.z + q0[h].w * k0.w
                 + q1[h].x * k1.x + q1[h].y * k1.y
                 + q1[h].z * k1.z + q1[h].w * k1.w;
        #pragma unroll
        for (int off = 8; off; off >>= 1) {
            #pragma unroll
            for (int h = 0; h < G; h++)
                s[h] += __shfl_xor_sync(0xffffffffu, s[h], off);
        }
        #pragma unroll
        for (int h = 0; h < G; h++) {
            const float v = s[h] * QK_SCALE;
            if (ok) {
                lmax[h] = fmaxf(lmax[h], v);
                if (sub == h) sprob[ta][h] = v;
            }
        }
    }

    // block max per head
    #pragma unroll
    for (int off = 16; off; off >>= 1) {
        #pragma unroll
        for (int h = 0; h < G; h++)
            lmax[h] = fmaxf(lmax[h], __shfl_xor_sync(0xffffffffu, lmax[h], off));
    }
    if (lane == 0) {
        #pragma unroll
        for (int h = 0; h < G; h++) swr[0][h][warp] = lmax[h];
    }
    __syncthreads();

    float gmax[G];
    #pragma unroll
    for (int h = 0; h < G; h++) {
        float v = -1e30f;
        #pragma unroll
        for (int w = 0; w < NWARPS; w++) v = fmaxf(v, swr[0][h][w]);
        gmax[h] = v;
    }

    // exp pass (token-strided, vectorized over heads) + block expsum
    float4* sprob4 = reinterpret_cast<float4*>(&sprob[0][0]);
    float pv[G] = {0.f, 0.f, 0.f, 0.f};
    for (int tk = tid; tk < nt; tk += NTHREADS) {
        float4 pr = sprob4[tk];
        pr.x = __expf(pr.x - gmax[0]);
        pr.y = __expf(pr.y - gmax[1]);
        pr.z = __expf(pr.z - gmax[2]);
        pr.w = __expf(pr.w - gmax[3]);
        sprob4[tk] = pr;
        pv[0] += pr.x; pv[1] += pr.y; pv[2] += pr.z; pv[3] += pr.w;
    }
    #pragma unroll
    for (int h = 0; h < G; h++) {
        float v = pv[h];
        #pragma unroll
        for (int off = 16; off; off >>= 1)
            v += __shfl_xor_sync(0xffffffffu, v, off);
        if (lane == 0) swr[1][h][warp] = v;
    }
    __syncthreads();   // probs visible for phase 2

    // ---- Phase 2: PV (warp-per-token, lane = d4), 4-way unrolled ----
    const int d4 = lane;
    float4 acc[G];
    #pragma unroll
    for (int h = 0; h < G; h++) acc[h] = make_float4(0.f, 0.f, 0.f, 0.f);

    int tt = warp;
    for (; tt + 3 * NWARPS < nt; tt += 4 * NWARPS) {
        #pragma unroll
        for (int u = 0; u < 4; u++) {
            const int tk  = tt + u * NWARPS;
            const int blk = sbt[tk >> 4];
            const float4 vv = reinterpret_cast<const float4*>(
                v_cache + ((((size_t)blk * BS + (tk & 15)) * KVH + kvh) * HEAD_DIM))[d4];
            const float4 pr = sprob4[tk];      // one LDS.128: all 4 head probs
            acc[0].x += pr.x * vv.x; acc[0].y += pr.x * vv.y;
            acc[0].z += pr.x * vv.z; acc[0].w += pr.x * vv.w;
            acc[1].x += pr.y * vv.x; acc[1].y += pr.y * vv.y;
            acc[1].z += pr.y * vv.z; acc[1].w += pr.y * vv.w;
            acc[2].x += pr.z * vv.x; acc[2].y += pr.z * vv.y;
            acc[2].z += pr.z * vv.z; acc[2].w += pr.z * vv.w;
            acc[3].x += pr.w * vv.x; acc[3].y += pr.w * vv.y;
            acc[3].z += pr.w * vv.z; acc[3].w += pr.w * vv.w;
        }
    }
    for (; tt < nt; tt += NWARPS) {
        const int blk = sbt[tt >> 4];
        const float4 vv = reinterpret_cast<const float4*>(
            v_cache + ((((size_t)blk * BS + (tt & 15)) * KVH + kvh) * HEAD_DIM))[d4];
        const float4 pr = sprob4[tt];
        acc[0].x += pr.x * vv.x; acc[0].y += pr.x * vv.y;
        acc[0].z += pr.x * vv.z; acc[0].w += pr.x * vv.w;
        acc[1].x += pr.y * vv.x; acc[1].y += pr.y * vv.y;
        acc[1].z += pr.y * vv.z; acc[1].w += pr.y * vv.w;
        acc[2].x += pr.z * vv.x; acc[2].y += pr.z * vv.y;
        acc[2].z += pr.z * vv.z; acc[2].w += pr.z * vv.w;
        acc[3].x += pr.w * vv.x; acc[3].y += pr.w * vv.y;
        acc[3].z += pr.w * vv.z; acc[3].w += pr.w * vv.w;
    }
    #pragma unroll
    for (int h = 0; h < G; h++)
        reinterpret_cast<float4*>(sacc[warp][h])[d4] = acc[h];
    __syncthreads();

    // combine warps + write partials
    const size_t base = ((size_t)(b * KVH + kvh) * NPART + p) * G;
    {
        const int h  = tid >> 5;                // 128 threads = G*32 exactly
        const int dd = tid & 31;
        float4 s = make_float4(0.f, 0.f, 0.f, 0.f);
        #pragma unroll
        for (int w = 0; w < NWARPS; w++) {
            const float4 x = reinterpret_cast<const float4*>(sacc[w][h])[dd];
            s.x += x.x; s.y += x.y; s.z += x.z; s.w += x.w;
        }
        reinterpret_cast<float4*>(g_pout + (base + h) * HEAD_DIM)[dd] = s;
    }
    if (tid < G) {
        float L = 0.f;
        #pragma unroll
        for (int w = 0; w < NWARPS; w++) L += swr[1][tid][w];
        g_pm[base + tid] = gmax[tid];
        g_pl[base + tid] = L;
    }
}

// ---------------------------------------------------------------------------
// Kernel 2: log-sum-exp combine, warp-per-(b, kvh, g). No smem, no block
// syncs: (m,l) loaded one-per-lane and shuffled; the <=NPART partition loads
// are independent (MLP = np). grid = 2048, block = 32.
// ---------------------------------------------------------------------------
__global__ __launch_bounds__(32) void pa_reduce_kernel(
    const int* __restrict__ context_lens,
    float*     __restrict__ out)            // [B, H, D]
{
    const int bkg  = blockIdx.x;            // (b*KVH + kvh)*G + g
    const int bk   = bkg >> 2;
    const int g    = bkg & 3;
    const int b    = bk / KVH;
    const int kvh  = bk % KVH;
    const int lane = threadIdx.x;

    const int ctx = __ldg(&context_lens[b]);
    const int np  = (ctx + CHUNK - 1) / CHUNK;

    const size_t base = (size_t)bk * NPART * G;

    // lane pi < np holds partition pi's (m, l)
    float m = -1e30f, l = 0.f;
    if (lane < np) {
        m = g_pm[base + lane * G + g];
        l = g_pl[base + lane * G + g];
    }

    // warp-wide global max
    float M = m;
    #pragma unroll
    for (int off = 16; off; off >>= 1)
        M = fmaxf(M, __shfl_xor_sync(0xffffffffu, M, off));

    // warp-wide L = sum l_pi * exp(m_pi - M)
    float Lp = (lane < np) ? l * __expf(m - M) : 0.f;
    #pragma unroll
    for (int off = 16; off; off >>= 1)
        Lp += __shfl_xor_sync(0xffffffffu, Lp, off);

    // accumulate partitions: lane = d4, loads independent across pi
    float4 acc = make_float4(0.f, 0.f, 0.f, 0.f);
    for (int pi = 0; pi < np; pi++) {
        const float mi = __shfl_sync(0xffffffffu, m, pi);
        const float s  = __expf(mi - M);
        const float4 a = reinterpret_cast<const float4*>(
            g_pout + (base + pi * G + g) * HEAD_DIM)[lane];
        acc.x += a.x * s; acc.y += a.y * s;
        acc.z += a.z * s; acc.w += a.w * s;
    }

    const float inv = 1.0f / Lp;
    reinterpret_cast<float4*>(
        out + (size_t)(b * NUM_HEADS + kvh * G + g) * HEAD_DIM)[lane] =
        make_float4(acc.x * inv, acc.y * inv, acc.z * inv, acc.w * inv);
}

extern "C" void kernel_launch(void* const* d_in, const int* in_sizes, int n_in,
                              void* d_out, int out_size) {
    const float* q            = (const float*)d_in[0];
    const float* k_cache      = (const float*)d_in[1];
    const float* v_cache      = (const float*)d_in[2];
    const int*   block_tables = (const int*)d_in[3];
    const int*   context_lens = (const int*)d_in[4];
    float* out = (float*)d_out;

    dim3 grid1(KVH, BATCH, NPART);
    pa_partial_kernel<<<grid1, NTHREADS>>>(q, k_cache, v_cache,
                                           block_tables, context_lens);
    pa_reduce_kernel<<<BATCH * KVH * G, 32>>>(context_lens, out);
}